// round 3
// baseline (speedup 1.0000x reference)
#include <cuda_runtime.h>
#include <cuda_bf16.h>

#define NNODES 100000
#define NEDGES 800000
#define ETOT   900000
#define MAXHC  240
#define MAXH   10
#define NEG_SLOPE 0.2f

// ---------------- scratch (device globals; no allocation allowed) ----------------
__device__ float    g_h   [NNODES * MAXHC];   // h = act(x) @ W
__device__ float    g_buf0[NNODES * MAXHC];   // layer outputs (ping)
__device__ float    g_buf1[NNODES * MAXHC];   // layer outputs (pong)
__device__ float    g_as  [NNODES * MAXH];    // alpha_src per node/head
__device__ float    g_ad  [NNODES * MAXH];    // alpha_dst per node/head
__device__ float    g_z   [NNODES * MAXH];    // segment sum of exp
__device__ float    g_e   [ETOT   * MAXH];    // per-edge exp values
__device__ unsigned g_smaxu[MAXH];            // per-head global max (encoded)

// ---------------- helpers ----------------
// order-preserving float->unsigned encoding (for max via unsigned atomicMax)
__device__ __forceinline__ unsigned enc_f(float v) {
    unsigned u = __float_as_uint(v);
    return (u & 0x80000000u) ? ~u : (u | 0x80000000u);
}
__device__ __forceinline__ float dec_f(unsigned u) {
    return __uint_as_float((u & 0x80000000u) ? (u ^ 0x80000000u) : ~u);
}

__device__ __forceinline__ void red_add_v4(float* addr, float4 v) {
    asm volatile("red.global.add.v4.f32 [%0], {%1,%2,%3,%4};"
                 :: "l"(addr), "f"(v.x), "f"(v.y), "f"(v.z), "f"(v.w) : "memory");
}

#define PACK2(out, lo, hi) \
    asm("mov.b64 %0, {%1, %2};" : "=l"(out) : "r"(__float_as_uint(lo)), "r"(__float_as_uint(hi)))
#define FMA2(d, a, b) \
    asm("fma.rn.f32x2 %0, %1, %2, %0;" : "+l"(d) : "l"(a), "l"(b))
#define UNPACK2(lo, hi, in) \
    asm("mov.b64 {%0, %1}, %2;" : "=r"(lo), "=r"(hi) : "l"(in))

// ---------------- init: zero out-buffer + reset per-head max ----------------
__global__ __launch_bounds__(256) void init_kernel(float* out, unsigned* smaxu,
                                                   int n_out) {
    int i = blockIdx.x * blockDim.x + threadIdx.x;
    if (i < n_out) out[i] = 0.0f;
    if (i < MAXH)  smaxu[i] = 0u;
}

// ---------------- SGEMM with packed f32x2 FMAs ----------------
// out[M,N] = act(A)[M,K] @ W[K,N];  act = bias? relu(a+bias[k]) : a
// BM=128, BN=64, BK=8, 256 threads, thread tile 8 rows x 4 cols (4 row-pairs).
__global__ __launch_bounds__(256) void gemm_act_kernel(
    const float* __restrict__ A, const float* __restrict__ W,
    const float* __restrict__ bias, float* __restrict__ out,
    int M, int K, int N)
{
    __shared__ float As[8][128];
    __shared__ float Bs[8][64];

    const int tid  = threadIdx.x;
    const int row0 = blockIdx.y * 128;
    const int col0 = blockIdx.x * 64;

    const int ty = tid >> 4;        // 0..15 -> 8 rows each
    const int tx = tid & 15;        // 0..15 -> 4 cols each

    const int arow = tid >> 1;              // 0..127
    const int acol = (tid & 1) * 4;         // 0 or 4
    const int brow = tid >> 5;              // 0..7
    const int bcol = (tid & 31) * 2;        // 0..62

    unsigned long long acc[4][4];           // [row-pair][col], each = 2 fp32 rows
#pragma unroll
    for (int i = 0; i < 4; i++)
#pragma unroll
        for (int j = 0; j < 4; j++) acc[i][j] = 0ULL;

    for (int k0 = 0; k0 < K; k0 += 8) {
        // --- load A tile (fused bias+relu of previous layer) ---
        float4 av = make_float4(0.f, 0.f, 0.f, 0.f);
        int gr = row0 + arow;
        if (gr < M) {
            av = *(const float4*)(A + (long)gr * K + k0 + acol);
            if (bias) {
                av.x = fmaxf(av.x + __ldg(bias + k0 + acol + 0), 0.f);
                av.y = fmaxf(av.y + __ldg(bias + k0 + acol + 1), 0.f);
                av.z = fmaxf(av.z + __ldg(bias + k0 + acol + 2), 0.f);
                av.w = fmaxf(av.w + __ldg(bias + k0 + acol + 3), 0.f);
            }
        }
        As[acol + 0][arow] = av.x;
        As[acol + 1][arow] = av.y;
        As[acol + 2][arow] = av.z;
        As[acol + 3][arow] = av.w;

        // --- load W tile ---
        float2 bv = make_float2(0.f, 0.f);
        int gc = col0 + bcol;
        if (gc + 1 < N)      bv = *(const float2*)(W + (long)(k0 + brow) * N + gc);
        else if (gc < N)     bv.x = W[(long)(k0 + brow) * N + gc];
        Bs[brow][bcol]     = bv.x;
        Bs[brow][bcol + 1] = bv.y;

        __syncthreads();

#pragma unroll
        for (int k = 0; k < 8; k++) {
            const unsigned long long* ap =
                (const unsigned long long*)&As[k][ty * 8];
            unsigned long long a01 = ap[0], a23 = ap[1], a45 = ap[2], a67 = ap[3];
            const float4 b4 = *(const float4*)&Bs[k][tx * 4];
            unsigned long long bb[4];
            PACK2(bb[0], b4.x, b4.x);
            PACK2(bb[1], b4.y, b4.y);
            PACK2(bb[2], b4.z, b4.z);
            PACK2(bb[3], b4.w, b4.w);
#pragma unroll
            for (int j = 0; j < 4; j++) {
                FMA2(acc[0][j], a01, bb[j]);
                FMA2(acc[1][j], a23, bb[j]);
                FMA2(acc[2][j], a45, bb[j]);
                FMA2(acc[3][j], a67, bb[j]);
            }
        }
        __syncthreads();
    }

#pragma unroll
    for (int i = 0; i < 4; i++) {
        int r0r = row0 + ty * 8 + 2 * i;
#pragma unroll
        for (int j = 0; j < 4; j++) {
            int c = col0 + tx * 4 + j;
            unsigned lo, hi;
            UNPACK2(lo, hi, acc[i][j]);
            if (c < N) {
                if (r0r     < M) out[(long)(r0r)     * N + c] = __uint_as_float(lo);
                if (r0r + 1 < M) out[(long)(r0r + 1) * N + c] = __uint_as_float(hi);
            }
        }
    }
}

// ---------------- alpha + z=0 + per-head global max (block pre-reduced) ----------------
__global__ __launch_bounds__(256) void alpha_kernel(
    const float* __restrict__ h, const float* __restrict__ a_s,
    const float* __restrict__ a_d, float* __restrict__ alpha_s,
    float* __restrict__ alpha_d, float* __restrict__ z,
    unsigned* __restrict__ smaxu, int H, int C)
{
    __shared__ unsigned s_max[MAXH];
    if (threadIdx.x < H) s_max[threadIdx.x] = 0u;   // 0 = encoded minimum
    __syncthreads();

    int idx = blockIdx.x * blockDim.x + threadIdx.x;
    if (idx < NNODES * H) {
        int node = idx / H;
        int hh = idx - node * H;
        const float4* hp  = (const float4*)(h + (long)node * H * C + hh * C);
        const float4* asp = (const float4*)(a_s + hh * C);
        const float4* adp = (const float4*)(a_d + hh * C);
        float ss = 0.f, sd = 0.f;
        int c4 = C >> 2;
        for (int c = 0; c < c4; c++) {
            float4 v = hp[c];
            float4 s4 = __ldg(asp + c);
            float4 d4 = __ldg(adp + c);
            ss += v.x * s4.x + v.y * s4.y + v.z * s4.z + v.w * s4.w;
            sd += v.x * d4.x + v.y * d4.y + v.z * d4.z + v.w * d4.w;
        }
        alpha_s[idx] = ss;
        alpha_d[idx] = sd;
        z[idx] = 0.0f;
        atomicMax(&s_max[hh], enc_f(ss));
    }
    __syncthreads();
    if (threadIdx.x < H)
        atomicMax(&smaxu[threadIdx.x], s_max[threadIdx.x]);
}

// ---------------- fused edge pass: e, exp(e - m_ub), segment-sum z ----------------
// m_ub[d,h] = leakyrelu(smax[h] + ad[d,h]) >= e for all src (monotone leakyrelu,
// smax >= as). Softmax is shift-invariant -> exact result, exp in (0,1].
__global__ __launch_bounds__(256) void edge_fused(
    const int* __restrict__ ei, const float* __restrict__ as,
    const float* __restrict__ ad, const unsigned* __restrict__ smaxu,
    float* __restrict__ ebuf, float* __restrict__ z, int H)
{
    int idx = blockIdx.x * blockDim.x + threadIdx.x;
    if (idx >= ETOT * H) return;
    int e  = idx / H;
    int hh = idx - e * H;
    int s, d;
    if (e < NEDGES) { s = __ldg(ei + e); d = __ldg(ei + NEDGES + e); }
    else            { s = e - NEDGES; d = s; }
    float asv = __ldg(as + s * H + hh);
    float adv = __ldg(ad + d * H + hh);
    float ev = asv + adv;
    ev = (ev > 0.f) ? ev : NEG_SLOPE * ev;
    float mb = dec_f(__ldg(smaxu + hh)) + adv;
    mb = (mb > 0.f) ? mb : NEG_SLOPE * mb;
    float ex = __expf(ev - mb);
    ebuf[idx] = ex;
    atomicAdd(&z[d * H + hh], ex);
}

// ---------------- scatter: one thread per (edge, head) ----------------
// attn computed once, then C/4 vec4 reductions into out[dst].
__global__ __launch_bounds__(256) void edge_scatter(
    const int* __restrict__ ei, const float* __restrict__ ex,
    const float* __restrict__ z, const float* __restrict__ h,
    float* __restrict__ out, int H, int c4 /* C/4 */, int HC)
{
    int idx = blockIdx.x * blockDim.x + threadIdx.x;
    if (idx >= ETOT * H) return;
    int e  = idx / H;
    int hh = idx - e * H;
    int s, d;
    if (e < NEDGES) { s = __ldg(ei + e); d = __ldg(ei + NEDGES + e); }
    else            { s = e - NEDGES; d = s; }
    float a = __ldg(ex + idx) * __frcp_rn(__ldg(z + d * H + hh));
    const float4* hp = (const float4*)(h + (long)s * HC) + (long)hh * c4;
    float*         op = out + (long)d * HC + (long)hh * c4 * 4;
#pragma unroll 3
    for (int q = 0; q < c4; q++) {
        float4 hv = hp[q];
        red_add_v4(op + q * 4, make_float4(hv.x * a, hv.y * a, hv.z * a, hv.w * a));
    }
}

// ---------------- epilogue: final relu(out + b) -> d_out ----------------
__global__ __launch_bounds__(256) void epilogue_kernel(
    const float* __restrict__ in, const float* __restrict__ bias,
    float* __restrict__ out, int n, int width)
{
    int i = blockIdx.x * blockDim.x + threadIdx.x;
    if (i >= n) return;
    out[i] = fmaxf(in[i] + __ldg(bias + (i % width)), 0.f);
}

// ---------------- host orchestration ----------------
extern "C" void kernel_launch(void* const* d_in, const int* in_sizes, int n_in,
                              void* d_out, int out_size)
{
    const float* x  = (const float*)d_in[0];
    const int*   ei = (const int*)d_in[1];
    // d_in[2] = edge_attr (unused by reference)

    float *h, *buf0, *buf1, *as, *ad, *z, *ebuf;
    unsigned* smaxu;
    {
        void* p;
        cudaGetSymbolAddress(&p, g_h);     h     = (float*)p;
        cudaGetSymbolAddress(&p, g_buf0);  buf0  = (float*)p;
        cudaGetSymbolAddress(&p, g_buf1);  buf1  = (float*)p;
        cudaGetSymbolAddress(&p, g_as);    as    = (float*)p;
        cudaGetSymbolAddress(&p, g_ad);    ad    = (float*)p;
        cudaGetSymbolAddress(&p, g_z);     z     = (float*)p;
        cudaGetSymbolAddress(&p, g_e);     ebuf  = (float*)p;
        cudaGetSymbolAddress(&p, g_smaxu); smaxu = (unsigned*)p;
    }

    const int DINS[5] = {32, 240, 120, 48, 24};
    const int CS[5]   = {24, 24, 24, 24, 12};
    const int HS[5]   = {10, 5, 2, 1, 1};

    const float* cur_in   = x;
    const float* cur_bias = nullptr;

    for (int i = 0; i < 5; i++) {
        int din = DINS[i], C = CS[i], H = HS[i], HC = H * C;
        const float* W   = (const float*)d_in[3 + 4 * i];
        const float* b   = (const float*)d_in[4 + 4 * i];
        const float* a_s = (const float*)d_in[5 + 4 * i];
        const float* a_d = (const float*)d_in[6 + 4 * i];
        float* outb = (i % 2 == 0) ? buf0 : buf1;

        // init out buffer + per-head max cells
        {
            int n_out = NNODES * HC;
            init_kernel<<<(n_out + 255) / 256, 256>>>(outb, smaxu, n_out);
        }

        // GEMM with fused bias+relu of previous layer on the A operand
        {
            dim3 grid((HC + 63) / 64, (NNODES + 127) / 128);
            gemm_act_kernel<<<grid, 256>>>(cur_in, W, cur_bias, h, NNODES, din, HC);
        }

        // alpha + z=0 + global per-head max (no separate reduce kernel)
        {
            int n = NNODES * H;
            alpha_kernel<<<(n + 255) / 256, 256>>>(h, a_s, a_d, as, ad, z, smaxu, H, C);
        }

        // fused edge pass (logit + exp + segment-sum)
        {
            int n = ETOT * H;
            edge_fused<<<(n + 255) / 256, 256>>>(ei, as, ad, smaxu, ebuf, z, H);
        }

        // weighted scatter with fused normalization, one thread per (edge, head)
        {
            int n = ETOT * H;
            edge_scatter<<<(n + 255) / 256, 256>>>(ei, ebuf, z, h, outb, H, C / 4, HC);
        }

        cur_in = outb;
        cur_bias = b;
    }

    // final relu(out + b4) -> d_out (100000 x 12 f32)
    {
        int n = NNODES * 12;
        epilogue_kernel<<<(n + 255) / 256, 256>>>(cur_in, cur_bias, (float*)d_out, n, 12);
    }
}

// round 4
// speedup vs baseline: 1.6046x; 1.6046x over previous
#include <cuda_runtime.h>
#include <cuda_bf16.h>

#define NNODES 100000
#define NEDGES 800000
#define ETOT   900000
#define MAXHC  240
#define MAXH   10
#define NEG_SLOPE 0.2f

// ---------------- scratch (device globals; no allocation allowed) ----------------
__device__ float    g_h   [NNODES * MAXHC];   // h = act(x) @ W
__device__ float    g_buf0[NNODES * MAXHC];   // layer outputs (ping)
__device__ float    g_buf1[NNODES * MAXHC];   // layer outputs (pong)
__device__ float    g_as  [NNODES * MAXH];    // alpha_src per node/head
__device__ float    g_ad  [NNODES * MAXH];    // alpha_dst per node/head
__device__ float    g_z   [NNODES * MAXH];    // segment sum of exp -> 1/z
__device__ float    g_e   [ETOT   * MAXH];    // per-edge exp values
__device__ unsigned g_smaxu[MAXH];            // per-head global max (encoded)

// ---------------- helpers ----------------
__device__ __forceinline__ unsigned enc_f(float v) {
    unsigned u = __float_as_uint(v);
    return (u & 0x80000000u) ? ~u : (u | 0x80000000u);
}
__device__ __forceinline__ float dec_f(unsigned u) {
    return __uint_as_float((u & 0x80000000u) ? (u ^ 0x80000000u) : ~u);
}

__device__ __forceinline__ void red_add_v4(float* addr, float4 v) {
    asm volatile("red.global.add.v4.f32 [%0], {%1,%2,%3,%4};"
                 :: "l"(addr), "f"(v.x), "f"(v.y), "f"(v.z), "f"(v.w) : "memory");
}

#define PACK2(out, lo, hi) \
    asm("mov.b64 %0, {%1, %2};" : "=l"(out) : "r"(__float_as_uint(lo)), "r"(__float_as_uint(hi)))
#define FMA2(d, a, b) \
    asm("fma.rn.f32x2 %0, %1, %2, %0;" : "+l"(d) : "l"(a), "l"(b))
#define UNPACK2(lo, hi, in) \
    asm("mov.b64 {%0, %1}, %2;" : "=r"(lo), "=r"(hi) : "l"(in))

// ---------------- init: zero out-buffer + reset per-head max ----------------
__global__ __launch_bounds__(256) void init_kernel(float* out, unsigned* smaxu,
                                                   int n_out) {
    int i = blockIdx.x * blockDim.x + threadIdx.x;
    if (i < n_out) out[i] = 0.0f;
    if (i < MAXH)  smaxu[i] = 0u;
}

// ---------------- SGEMM with packed f32x2 FMAs ----------------
__global__ __launch_bounds__(256) void gemm_act_kernel(
    const float* __restrict__ A, const float* __restrict__ W,
    const float* __restrict__ bias, float* __restrict__ out,
    int M, int K, int N)
{
    __shared__ float As[8][128];
    __shared__ float Bs[8][64];

    const int tid  = threadIdx.x;
    const int row0 = blockIdx.y * 128;
    const int col0 = blockIdx.x * 64;

    const int ty = tid >> 4;
    const int tx = tid & 15;

    const int arow = tid >> 1;
    const int acol = (tid & 1) * 4;
    const int brow = tid >> 5;
    const int bcol = (tid & 31) * 2;

    unsigned long long acc[4][4];
#pragma unroll
    for (int i = 0; i < 4; i++)
#pragma unroll
        for (int j = 0; j < 4; j++) acc[i][j] = 0ULL;

    for (int k0 = 0; k0 < K; k0 += 8) {
        float4 av = make_float4(0.f, 0.f, 0.f, 0.f);
        int gr = row0 + arow;
        if (gr < M) {
            av = *(const float4*)(A + (long)gr * K + k0 + acol);
            if (bias) {
                av.x = fmaxf(av.x + __ldg(bias + k0 + acol + 0), 0.f);
                av.y = fmaxf(av.y + __ldg(bias + k0 + acol + 1), 0.f);
                av.z = fmaxf(av.z + __ldg(bias + k0 + acol + 2), 0.f);
                av.w = fmaxf(av.w + __ldg(bias + k0 + acol + 3), 0.f);
            }
        }
        As[acol + 0][arow] = av.x;
        As[acol + 1][arow] = av.y;
        As[acol + 2][arow] = av.z;
        As[acol + 3][arow] = av.w;

        float2 bv = make_float2(0.f, 0.f);
        int gc = col0 + bcol;
        if (gc + 1 < N)      bv = *(const float2*)(W + (long)(k0 + brow) * N + gc);
        else if (gc < N)     bv.x = W[(long)(k0 + brow) * N + gc];
        Bs[brow][bcol]     = bv.x;
        Bs[brow][bcol + 1] = bv.y;

        __syncthreads();

#pragma unroll
        for (int k = 0; k < 8; k++) {
            const unsigned long long* ap =
                (const unsigned long long*)&As[k][ty * 8];
            unsigned long long a01 = ap[0], a23 = ap[1], a45 = ap[2], a67 = ap[3];
            const float4 b4 = *(const float4*)&Bs[k][tx * 4];
            unsigned long long bb[4];
            PACK2(bb[0], b4.x, b4.x);
            PACK2(bb[1], b4.y, b4.y);
            PACK2(bb[2], b4.z, b4.z);
            PACK2(bb[3], b4.w, b4.w);
#pragma unroll
            for (int j = 0; j < 4; j++) {
                FMA2(acc[0][j], a01, bb[j]);
                FMA2(acc[1][j], a23, bb[j]);
                FMA2(acc[2][j], a45, bb[j]);
                FMA2(acc[3][j], a67, bb[j]);
            }
        }
        __syncthreads();
    }

#pragma unroll
    for (int i = 0; i < 4; i++) {
        int r0r = row0 + ty * 8 + 2 * i;
#pragma unroll
        for (int j = 0; j < 4; j++) {
            int c = col0 + tx * 4 + j;
            unsigned lo, hi;
            UNPACK2(lo, hi, acc[i][j]);
            if (c < N) {
                if (r0r     < M) out[(long)(r0r)     * N + c] = __uint_as_float(lo);
                if (r0r + 1 < M) out[(long)(r0r + 1) * N + c] = __uint_as_float(hi);
            }
        }
    }
}

// ---------------- alpha + z=0 + per-head global max ----------------
template<int H, int C>
__global__ __launch_bounds__(256) void alpha_kernel(
    const float* __restrict__ h, const float* __restrict__ a_s,
    const float* __restrict__ a_d, float* __restrict__ alpha_s,
    float* __restrict__ alpha_d, float* __restrict__ z,
    unsigned* __restrict__ smaxu)
{
    __shared__ unsigned s_max[H];
    if (threadIdx.x < H) s_max[threadIdx.x] = 0u;
    __syncthreads();

    int idx = blockIdx.x * blockDim.x + threadIdx.x;
    if (idx < NNODES * H) {
        int node = idx / H;
        int hh = idx - node * H;
        const float4* hp  = (const float4*)(h + (long)node * H * C + hh * C);
        const float4* asp = (const float4*)(a_s + hh * C);
        const float4* adp = (const float4*)(a_d + hh * C);
        float ss = 0.f, sd = 0.f;
#pragma unroll
        for (int c = 0; c < C / 4; c++) {
            float4 v = hp[c];
            float4 s4 = __ldg(asp + c);
            float4 d4 = __ldg(adp + c);
            ss += v.x * s4.x + v.y * s4.y + v.z * s4.z + v.w * s4.w;
            sd += v.x * d4.x + v.y * d4.y + v.z * d4.z + v.w * d4.w;
        }
        alpha_s[idx] = ss;
        alpha_d[idx] = sd;
        z[idx] = 0.0f;
        atomicMax(&s_max[hh], enc_f(ss));
    }
    __syncthreads();
    if (threadIdx.x < H)
        atomicMax(&smaxu[threadIdx.x], s_max[threadIdx.x]);
}

// ---------------- fused edge pass: e, exp(e - m_ub), segment-sum z ----------------
template<int H>
__global__ __launch_bounds__(256) void edge_fused(
    const int* __restrict__ ei, const float* __restrict__ as,
    const float* __restrict__ ad, const unsigned* __restrict__ smaxu,
    float* __restrict__ ebuf, float* __restrict__ z)
{
    int idx = blockIdx.x * blockDim.x + threadIdx.x;
    if (idx >= ETOT * H) return;
    int e  = idx / H;                 // compile-time constant divisor
    int hh = idx - e * H;
    int s, d;
    if (e < NEDGES) { s = __ldg(ei + e); d = __ldg(ei + NEDGES + e); }
    else            { s = e - NEDGES; d = s; }
    float asv = __ldg(as + s * H + hh);
    float adv = __ldg(ad + d * H + hh);
    float ev = asv + adv;
    ev = (ev > 0.f) ? ev : NEG_SLOPE * ev;
    float mb = dec_f(__ldg(smaxu + hh)) + adv;
    mb = (mb > 0.f) ? mb : NEG_SLOPE * mb;
    float ex = __expf(ev - mb);
    ebuf[idx] = ex;
    atomicAdd(&z[d * H + hh], ex);
}

// ---------------- invert z in place (z > 0 guaranteed by self-loops) ----------------
__global__ __launch_bounds__(256) void recip_kernel(float* z, int n) {
    int i = blockIdx.x * blockDim.x + threadIdx.x;
    if (i < n) z[i] = __frcp_rn(z[i]);
}

// ---------------- scatter: one thread per (edge, 4-wide chunk) ----------------
// coalesced: consecutive threads cover consecutive chunks of one edge's h row.
template<int H, int C>
__global__ __launch_bounds__(256) void edge_scatter(
    const int* __restrict__ ei, const float* __restrict__ ex,
    const float* __restrict__ rz, const float* __restrict__ h,
    float* __restrict__ out)
{
    constexpr int NCH = H * C / 4;    // chunks per edge
    constexpr int HC  = H * C;
    long idx = (long)blockIdx.x * blockDim.x + threadIdx.x;
    if (idx >= (long)ETOT * NCH) return;
    int e = (int)(idx / NCH);         // compile-time constant divisor
    int q = (int)(idx - (long)e * NCH);
    int s, d;
    if (e < NEDGES) { s = __ldg(ei + e); d = __ldg(ei + NEDGES + e); }
    else            { s = e - NEDGES; d = s; }
    int head = q / (C / 4);           // compile-time constant divisor
    float a = __ldg(ex + (long)e * H + head) * __ldg(rz + (long)d * H + head);
    float4 hv = *(const float4*)(h + (long)s * HC + q * 4);
    red_add_v4(out + (long)d * HC + q * 4,
               make_float4(hv.x * a, hv.y * a, hv.z * a, hv.w * a));
}

// ---------------- epilogue: final relu(out + b) -> d_out ----------------
__global__ __launch_bounds__(256) void epilogue_kernel(
    const float* __restrict__ in, const float* __restrict__ bias,
    float* __restrict__ out, int n, int width)
{
    int i = blockIdx.x * blockDim.x + threadIdx.x;
    if (i >= n) return;
    out[i] = fmaxf(in[i] + __ldg(bias + (i % width)), 0.f);
}

// ---------------- per-layer templated driver ----------------
template<int H, int C>
static void run_layer(const float* cur_in, const float* cur_bias, int din,
                      const float* W, const float* a_s, const float* a_d,
                      const int* ei, float* h, float* as, float* ad,
                      float* z, float* ebuf, unsigned* smaxu, float* outb)
{
    constexpr int HC = H * C;
    {
        int n_out = NNODES * HC;
        init_kernel<<<(n_out + 255) / 256, 256>>>(outb, smaxu, n_out);
    }
    {
        dim3 grid((HC + 63) / 64, (NNODES + 127) / 128);
        gemm_act_kernel<<<grid, 256>>>(cur_in, W, cur_bias, h, NNODES, din, HC);
    }
    {
        int n = NNODES * H;
        alpha_kernel<H, C><<<(n + 255) / 256, 256>>>(h, a_s, a_d, as, ad, z, smaxu);
    }
    {
        int n = ETOT * H;
        edge_fused<H><<<(n + 255) / 256, 256>>>(ei, as, ad, smaxu, ebuf, z);
    }
    {
        int n = NNODES * H;
        recip_kernel<<<(n + 255) / 256, 256>>>(z, n);
    }
    {
        long total = (long)ETOT * (HC / 4);
        int blocks = (int)((total + 255) / 256);
        edge_scatter<H, C><<<blocks, 256>>>(ei, ebuf, z, h, outb);
    }
}

// ---------------- host orchestration ----------------
extern "C" void kernel_launch(void* const* d_in, const int* in_sizes, int n_in,
                              void* d_out, int out_size)
{
    const float* x  = (const float*)d_in[0];
    const int*   ei = (const int*)d_in[1];

    float *h, *buf0, *buf1, *as, *ad, *z, *ebuf;
    unsigned* smaxu;
    {
        void* p;
        cudaGetSymbolAddress(&p, g_h);     h     = (float*)p;
        cudaGetSymbolAddress(&p, g_buf0);  buf0  = (float*)p;
        cudaGetSymbolAddress(&p, g_buf1);  buf1  = (float*)p;
        cudaGetSymbolAddress(&p, g_as);    as    = (float*)p;
        cudaGetSymbolAddress(&p, g_ad);    ad    = (float*)p;
        cudaGetSymbolAddress(&p, g_z);     z     = (float*)p;
        cudaGetSymbolAddress(&p, g_e);     ebuf  = (float*)p;
        cudaGetSymbolAddress(&p, g_smaxu); smaxu = (unsigned*)p;
    }

    const int DINS[5] = {32, 240, 120, 48, 24};

    const float* W[5]; const float* B[5]; const float* AS[5]; const float* AD[5];
    for (int i = 0; i < 5; i++) {
        W[i]  = (const float*)d_in[3 + 4 * i];
        B[i]  = (const float*)d_in[4 + 4 * i];
        AS[i] = (const float*)d_in[5 + 4 * i];
        AD[i] = (const float*)d_in[6 + 4 * i];
    }

    run_layer<10, 24>(x,    nullptr, DINS[0], W[0], AS[0], AD[0], ei, h, as, ad, z, ebuf, smaxu, buf0);
    run_layer< 5, 24>(buf0, B[0],    DINS[1], W[1], AS[1], AD[1], ei, h, as, ad, z, ebuf, smaxu, buf1);
    run_layer< 2, 24>(buf1, B[1],    DINS[2], W[2], AS[2], AD[2], ei, h, as, ad, z, ebuf, smaxu, buf0);
    run_layer< 1, 24>(buf0, B[2],    DINS[3], W[3], AS[3], AD[3], ei, h, as, ad, z, ebuf, smaxu, buf1);
    run_layer< 1, 12>(buf1, B[3],    DINS[4], W[4], AS[4], AD[4], ei, h, as, ad, z, ebuf, smaxu, buf0);

    {
        int n = NNODES * 12;
        epilogue_kernel<<<(n + 255) / 256, 256>>>(buf0, B[4], (float*)d_out, n, 12);
    }
}

// round 5
// speedup vs baseline: 2.2268x; 1.3878x over previous
#include <cuda_runtime.h>
#include <cuda_bf16.h>

#define NNODES 100000
#define NEDGES 800000
#define ETOT   900000
#define MAXHC  240
#define MAXH   10
#define NEG_SLOPE 0.2f
#define SCAN_BLK 1024
#define NSCAN ((NNODES + SCAN_BLK - 1) / SCAN_BLK)   // 98

// ---------------- scratch (device globals; no allocation allowed) ----------------
__device__ float    g_h   [NNODES * MAXHC];
__device__ float    g_buf0[NNODES * MAXHC];
__device__ float    g_buf1[NNODES * MAXHC];
__device__ float    g_as  [NNODES * MAXH];
__device__ float    g_ad  [NNODES * MAXH];
__device__ float    g_z   [NNODES * MAXH];      // segsum of exp -> 1/z
__device__ float    g_e   [ETOT   * MAXH];      // per-edge exp values
__device__ unsigned g_smaxu[MAXH];              // per-head global max (encoded)
// CSR (built once per launch)
__device__ int g_rowptr [NNODES + 1];
__device__ int g_cnt    [NNODES];
__device__ int g_fill   [NNODES];
__device__ int g_csr_src[ETOT];
__device__ int g_csr_eid[ETOT];
__device__ int g_bsum   [NSCAN];

// ---------------- helpers ----------------
__device__ __forceinline__ unsigned enc_f(float v) {
    unsigned u = __float_as_uint(v);
    return (u & 0x80000000u) ? ~u : (u | 0x80000000u);
}
__device__ __forceinline__ float dec_f(unsigned u) {
    return __uint_as_float((u & 0x80000000u) ? (u ^ 0x80000000u) : ~u);
}

#define PACK2(out, lo, hi) \
    asm("mov.b64 %0, {%1, %2};" : "=l"(out) : "r"(__float_as_uint(lo)), "r"(__float_as_uint(hi)))
#define FMA2(d, a, b) \
    asm("fma.rn.f32x2 %0, %1, %2, %0;" : "+l"(d) : "l"(a), "l"(b))
#define UNPACK2(lo, hi, in) \
    asm("mov.b64 {%0, %1}, %2;" : "=r"(lo), "=r"(hi) : "l"(in))

// ================= CSR build (once per launch) =================
__global__ __launch_bounds__(256) void csr_zero(int* cnt, int* fill, unsigned* smaxu) {
    int i = blockIdx.x * blockDim.x + threadIdx.x;
    if (i < NNODES) { cnt[i] = 0; fill[i] = 0; }
    if (i < MAXH) smaxu[i] = 0u;
}

__global__ __launch_bounds__(256) void csr_hist(const int* __restrict__ ei, int* cnt) {
    int e = blockIdx.x * blockDim.x + threadIdx.x;
    if (e >= ETOT) return;
    int d = (e < NEDGES) ? __ldg(ei + NEDGES + e) : (e - NEDGES);
    atomicAdd(&cnt[d], 1);
}

// per-block exclusive scan; writes partial prefix + block sums
__global__ __launch_bounds__(SCAN_BLK) void csr_scan1(const int* __restrict__ cnt,
                                                      int* rowptr, int* bsum) {
    __shared__ int sh[SCAN_BLK];
    int gi = blockIdx.x * SCAN_BLK + threadIdx.x;
    int v = (gi < NNODES) ? cnt[gi] : 0;
    sh[threadIdx.x] = v;
    __syncthreads();
    // Hillis-Steele inclusive scan
    for (int off = 1; off < SCAN_BLK; off <<= 1) {
        int t = (threadIdx.x >= off) ? sh[threadIdx.x - off] : 0;
        __syncthreads();
        sh[threadIdx.x] += t;
        __syncthreads();
    }
    if (gi < NNODES) rowptr[gi] = sh[threadIdx.x] - v;   // exclusive
    if (threadIdx.x == SCAN_BLK - 1) bsum[blockIdx.x] = sh[threadIdx.x];
}

__global__ void csr_scan2(int* bsum) {
    if (threadIdx.x == 0 && blockIdx.x == 0) {
        int acc = 0;
        for (int i = 0; i < NSCAN; i++) { int t = bsum[i]; bsum[i] = acc; acc += t; }
    }
}

__global__ __launch_bounds__(SCAN_BLK) void csr_scan3(int* rowptr, const int* __restrict__ bsum) {
    int gi = blockIdx.x * SCAN_BLK + threadIdx.x;
    if (gi < NNODES) rowptr[gi] += bsum[blockIdx.x];
    if (gi == 0) rowptr[NNODES] = ETOT;
}

__global__ __launch_bounds__(256) void csr_fill(const int* __restrict__ ei,
                                                const int* __restrict__ rowptr,
                                                int* fill, int* csr_src, int* csr_eid) {
    int e = blockIdx.x * blockDim.x + threadIdx.x;
    if (e >= ETOT) return;
    int s, d;
    if (e < NEDGES) { s = __ldg(ei + e); d = __ldg(ei + NEDGES + e); }
    else            { s = e - NEDGES; d = s; }
    int pos = rowptr[d] + atomicAdd(&fill[d], 1);
    csr_src[pos] = s;
    csr_eid[pos] = e;
}

// ================= SGEMM with packed f32x2 FMAs =================
__global__ __launch_bounds__(256) void gemm_act_kernel(
    const float* __restrict__ A, const float* __restrict__ W,
    const float* __restrict__ bias, float* __restrict__ out,
    int M, int K, int N)
{
    __shared__ float As[8][128];
    __shared__ float Bs[8][64];

    const int tid  = threadIdx.x;
    const int row0 = blockIdx.y * 128;
    const int col0 = blockIdx.x * 64;

    const int ty = tid >> 4;
    const int tx = tid & 15;

    const int arow = tid >> 1;
    const int acol = (tid & 1) * 4;
    const int brow = tid >> 5;
    const int bcol = (tid & 31) * 2;

    unsigned long long acc[4][4];
#pragma unroll
    for (int i = 0; i < 4; i++)
#pragma unroll
        for (int j = 0; j < 4; j++) acc[i][j] = 0ULL;

    for (int k0 = 0; k0 < K; k0 += 8) {
        float4 av = make_float4(0.f, 0.f, 0.f, 0.f);
        int gr = row0 + arow;
        if (gr < M) {
            av = *(const float4*)(A + (long)gr * K + k0 + acol);
            if (bias) {
                av.x = fmaxf(av.x + __ldg(bias + k0 + acol + 0), 0.f);
                av.y = fmaxf(av.y + __ldg(bias + k0 + acol + 1), 0.f);
                av.z = fmaxf(av.z + __ldg(bias + k0 + acol + 2), 0.f);
                av.w = fmaxf(av.w + __ldg(bias + k0 + acol + 3), 0.f);
            }
        }
        As[acol + 0][arow] = av.x;
        As[acol + 1][arow] = av.y;
        As[acol + 2][arow] = av.z;
        As[acol + 3][arow] = av.w;

        float2 bv = make_float2(0.f, 0.f);
        int gc = col0 + bcol;
        if (gc + 1 < N)      bv = *(const float2*)(W + (long)(k0 + brow) * N + gc);
        else if (gc < N)     bv.x = W[(long)(k0 + brow) * N + gc];
        Bs[brow][bcol]     = bv.x;
        Bs[brow][bcol + 1] = bv.y;

        __syncthreads();

#pragma unroll
        for (int k = 0; k < 8; k++) {
            const unsigned long long* ap =
                (const unsigned long long*)&As[k][ty * 8];
            unsigned long long a01 = ap[0], a23 = ap[1], a45 = ap[2], a67 = ap[3];
            const float4 b4 = *(const float4*)&Bs[k][tx * 4];
            unsigned long long bb[4];
            PACK2(bb[0], b4.x, b4.x);
            PACK2(bb[1], b4.y, b4.y);
            PACK2(bb[2], b4.z, b4.z);
            PACK2(bb[3], b4.w, b4.w);
#pragma unroll
            for (int j = 0; j < 4; j++) {
                FMA2(acc[0][j], a01, bb[j]);
                FMA2(acc[1][j], a23, bb[j]);
                FMA2(acc[2][j], a45, bb[j]);
                FMA2(acc[3][j], a67, bb[j]);
            }
        }
        __syncthreads();
    }

#pragma unroll
    for (int i = 0; i < 4; i++) {
        int r0r = row0 + ty * 8 + 2 * i;
#pragma unroll
        for (int j = 0; j < 4; j++) {
            int c = col0 + tx * 4 + j;
            unsigned lo, hi;
            UNPACK2(lo, hi, acc[i][j]);
            if (c < N) {
                if (r0r     < M) out[(long)(r0r)     * N + c] = __uint_as_float(lo);
                if (r0r + 1 < M) out[(long)(r0r + 1) * N + c] = __uint_as_float(hi);
            }
        }
    }
}

// ================= alpha + z=0 + per-head global max =================
template<int H, int C>
__global__ __launch_bounds__(256) void alpha_kernel(
    const float* __restrict__ h, const float* __restrict__ a_s,
    const float* __restrict__ a_d, float* __restrict__ alpha_s,
    float* __restrict__ alpha_d, float* __restrict__ z,
    unsigned* __restrict__ smaxu)
{
    __shared__ unsigned s_max[H];
    if (threadIdx.x < H) s_max[threadIdx.x] = 0u;
    __syncthreads();

    int idx = blockIdx.x * blockDim.x + threadIdx.x;
    if (idx < NNODES * H) {
        int node = idx / H;
        int hh = idx - node * H;
        const float4* hp  = (const float4*)(h + (long)node * H * C + hh * C);
        const float4* asp = (const float4*)(a_s + hh * C);
        const float4* adp = (const float4*)(a_d + hh * C);
        float ss = 0.f, sd = 0.f;
#pragma unroll
        for (int c = 0; c < C / 4; c++) {
            float4 v = hp[c];
            float4 s4 = __ldg(asp + c);
            float4 d4 = __ldg(adp + c);
            ss += v.x * s4.x + v.y * s4.y + v.z * s4.z + v.w * s4.w;
            sd += v.x * d4.x + v.y * d4.y + v.z * d4.z + v.w * d4.w;
        }
        alpha_s[idx] = ss;
        alpha_d[idx] = sd;
        z[idx] = 0.0f;
        atomicMax(&s_max[hh], enc_f(ss));
    }
    __syncthreads();
    if (threadIdx.x < H)
        atomicMax(&smaxu[threadIdx.x], s_max[threadIdx.x]);
}

// ================= fused edge pass: exp(e - m_ub), segsum z =================
template<int H>
__global__ __launch_bounds__(256) void edge_fused(
    const int* __restrict__ ei, const float* __restrict__ as,
    const float* __restrict__ ad, const unsigned* __restrict__ smaxu,
    float* __restrict__ ebuf, float* __restrict__ z)
{
    int idx = blockIdx.x * blockDim.x + threadIdx.x;
    if (idx >= ETOT * H) return;
    int e  = idx / H;
    int hh = idx - e * H;
    int s, d;
    if (e < NEDGES) { s = __ldg(ei + e); d = __ldg(ei + NEDGES + e); }
    else            { s = e - NEDGES; d = s; }
    float asv = __ldg(as + s * H + hh);
    float adv = __ldg(ad + d * H + hh);
    float ev = asv + adv;
    ev = (ev > 0.f) ? ev : NEG_SLOPE * ev;
    float mb = dec_f(__ldg(smaxu + hh)) + adv;
    mb = (mb > 0.f) ? mb : NEG_SLOPE * mb;
    float ex = __expf(ev - mb);
    ebuf[idx] = ex;
    atomicAdd(&z[d * H + hh], ex);
}

// ================= z -> 1/z in place; reset smaxu for next layer =================
__global__ __launch_bounds__(256) void recip_kernel(float* z, unsigned* smaxu, int n) {
    int i = blockIdx.x * blockDim.x + threadIdx.x;
    if (i < n) z[i] = __frcp_rn(z[i]);
    if (i < MAXH) smaxu[i] = 0u;
}

// ================= CSR gather: out[n] = rz[n] * sum_in-edges ex*h[src] =================
// one thread per (node, 4-wide chunk): coalesced read of h rows, coalesced
// single write, zero atomics, no output init required.
template<int H, int C>
__global__ __launch_bounds__(256) void node_gather(
    const int* __restrict__ rowptr, const int* __restrict__ csr_src,
    const int* __restrict__ csr_eid, const float* __restrict__ ex,
    const float* __restrict__ rz, const float* __restrict__ h,
    float* __restrict__ out)
{
    constexpr int NCH = H * C / 4;
    constexpr int HC  = H * C;
    long idx = (long)blockIdx.x * blockDim.x + threadIdx.x;
    if (idx >= (long)NNODES * NCH) return;
    int n = (int)(idx / NCH);
    int q = (int)(idx - (long)n * NCH);
    int head = q / (C / 4);

    int beg = __ldg(rowptr + n);
    int end = __ldg(rowptr + n + 1);
    float4 acc = make_float4(0.f, 0.f, 0.f, 0.f);
    for (int j = beg; j < end; j++) {
        int s   = __ldg(csr_src + j);
        int eid = __ldg(csr_eid + j);
        float a = __ldg(ex + (long)eid * H + head);
        float4 hv = *(const float4*)(h + (long)s * HC + q * 4);
        acc.x += hv.x * a; acc.y += hv.y * a;
        acc.z += hv.z * a; acc.w += hv.w * a;
    }
    float rzv = __ldg(rz + (long)n * H + head);
    *(float4*)(out + (long)n * HC + q * 4) =
        make_float4(acc.x * rzv, acc.y * rzv, acc.z * rzv, acc.w * rzv);
}

// ================= epilogue =================
__global__ __launch_bounds__(256) void epilogue_kernel(
    const float* __restrict__ in, const float* __restrict__ bias,
    float* __restrict__ out, int n, int width)
{
    int i = blockIdx.x * blockDim.x + threadIdx.x;
    if (i >= n) return;
    out[i] = fmaxf(in[i] + __ldg(bias + (i % width)), 0.f);
}

// ================= per-layer templated driver =================
template<int H, int C>
static void run_layer(const float* cur_in, const float* cur_bias, int din,
                      const float* W, const float* a_s, const float* a_d,
                      const int* ei, float* h, float* as, float* ad,
                      float* z, float* ebuf, unsigned* smaxu,
                      const int* rowptr, const int* csr_src, const int* csr_eid,
                      float* outb)
{
    constexpr int HC = H * C;
    {
        dim3 grid((HC + 63) / 64, (NNODES + 127) / 128);
        gemm_act_kernel<<<grid, 256>>>(cur_in, W, cur_bias, h, NNODES, din, HC);
    }
    {
        int n = NNODES * H;
        alpha_kernel<H, C><<<(n + 255) / 256, 256>>>(h, a_s, a_d, as, ad, z, smaxu);
    }
    {
        int n = ETOT * H;
        edge_fused<H><<<(n + 255) / 256, 256>>>(ei, as, ad, smaxu, ebuf, z);
    }
    {
        int n = NNODES * H;
        recip_kernel<<<(n + 255) / 256, 256>>>(z, smaxu, n);
    }
    {
        long total = (long)NNODES * (HC / 4);
        int blocks = (int)((total + 255) / 256);
        node_gather<H, C><<<blocks, 256>>>(rowptr, csr_src, csr_eid, ebuf, z, h, outb);
    }
}

// ================= host orchestration =================
extern "C" void kernel_launch(void* const* d_in, const int* in_sizes, int n_in,
                              void* d_out, int out_size)
{
    const float* x  = (const float*)d_in[0];
    const int*   ei = (const int*)d_in[1];

    float *h, *buf0, *buf1, *as, *ad, *z, *ebuf;
    unsigned* smaxu;
    int *rowptr, *cnt, *fill, *csr_src, *csr_eid, *bsum;
    {
        void* p;
        cudaGetSymbolAddress(&p, g_h);       h       = (float*)p;
        cudaGetSymbolAddress(&p, g_buf0);    buf0    = (float*)p;
        cudaGetSymbolAddress(&p, g_buf1);    buf1    = (float*)p;
        cudaGetSymbolAddress(&p, g_as);      as      = (float*)p;
        cudaGetSymbolAddress(&p, g_ad);      ad      = (float*)p;
        cudaGetSymbolAddress(&p, g_z);       z       = (float*)p;
        cudaGetSymbolAddress(&p, g_e);       ebuf    = (float*)p;
        cudaGetSymbolAddress(&p, g_smaxu);   smaxu   = (unsigned*)p;
        cudaGetSymbolAddress(&p, g_rowptr);  rowptr  = (int*)p;
        cudaGetSymbolAddress(&p, g_cnt);     cnt     = (int*)p;
        cudaGetSymbolAddress(&p, g_fill);    fill    = (int*)p;
        cudaGetSymbolAddress(&p, g_csr_src); csr_src = (int*)p;
        cudaGetSymbolAddress(&p, g_csr_eid); csr_eid = (int*)p;
        cudaGetSymbolAddress(&p, g_bsum);    bsum    = (int*)p;
    }

    // ---- CSR build (graph identical for all 5 layers) ----
    csr_zero<<<(NNODES + 255) / 256, 256>>>(cnt, fill, smaxu);
    csr_hist<<<(ETOT + 255) / 256, 256>>>(ei, cnt);
    csr_scan1<<<NSCAN, SCAN_BLK>>>(cnt, rowptr, bsum);
    csr_scan2<<<1, 32>>>(bsum);
    csr_scan3<<<NSCAN, SCAN_BLK>>>(rowptr, bsum);
    csr_fill<<<(ETOT + 255) / 256, 256>>>(ei, rowptr, fill, csr_src, csr_eid);

    const int DINS[5] = {32, 240, 120, 48, 24};
    const float* W[5]; const float* B[5]; const float* AS[5]; const float* AD[5];
    for (int i = 0; i < 5; i++) {
        W[i]  = (const float*)d_in[3 + 4 * i];
        B[i]  = (const float*)d_in[4 + 4 * i];
        AS[i] = (const float*)d_in[5 + 4 * i];
        AD[i] = (const float*)d_in[6 + 4 * i];
    }

    run_layer<10, 24>(x,    nullptr, DINS[0], W[0], AS[0], AD[0], ei, h, as, ad, z, ebuf, smaxu, rowptr, csr_src, csr_eid, buf0);
    run_layer< 5, 24>(buf0, B[0],    DINS[1], W[1], AS[1], AD[1], ei, h, as, ad, z, ebuf, smaxu, rowptr, csr_src, csr_eid, buf1);
    run_layer< 2, 24>(buf1, B[1],    DINS[2], W[2], AS[2], AD[2], ei, h, as, ad, z, ebuf, smaxu, rowptr, csr_src, csr_eid, buf0);
    run_layer< 1, 24>(buf0, B[2],    DINS[3], W[3], AS[3], AD[3], ei, h, as, ad, z, ebuf, smaxu, rowptr, csr_src, csr_eid, buf1);
    run_layer< 1, 12>(buf1, B[3],    DINS[4], W[4], AS[4], AD[4], ei, h, as, ad, z, ebuf, smaxu, rowptr, csr_src, csr_eid, buf0);

    {
        int n = NNODES * 12;
        epilogue_kernel<<<(n + 255) / 256, 256>>>(buf0, B[4], (float*)d_out, n, 12);
    }
}